// round 4
// baseline (speedup 1.0000x reference)
#include <cuda_runtime.h>

#define Bn 16
#define Cn 32
#define Sn 256
#define Mn 12
#define Rn 24
#define Ln 4
#define BCn (Bn*Cn)
#define WTN (Ln*Rn*Mn*Cn*Cn)   // 1,179,648

// ---- scratch (device globals: no allocation allowed) ----
__device__ float g_h[(size_t)BCn*Sn*Sn];           // 134 MB, updated in place
__device__ float g_Y[(size_t)BCn*Sn*(2*Mn)];       // [bc][h][q] q<12: re, q>=12: im
__device__ float g_T[(size_t)Bn*Sn*Cn*(2*Mn)];     // [b][y][o][q] q<12: re, q>=12: im
__device__ float g_Wtr[WTN];                       // [l][r][k][i][o], scaled
__device__ float g_Wti[WTN];
__device__ float g_trig[Rn*Sn];                    // rows 0-11 cos(2pi k w/256), 12-23 sin
__device__ float g_ch[Rn*Sn];                      // cos(2pi ky h/256), ky in {0..11,244..255}
__device__ float g_sh[Rn*Sn];

__global__ void k_setup() {
    int q = blockIdx.x, w = threadIdx.x;
    float s, c;
    int kq = (q < Mn) ? q : q - Mn;
    sincospif((float)((kq*w) & 255) * (2.0f/256.0f), &s, &c);
    g_trig[q*Sn + w] = (q < Mn) ? c : s;
    int ky = (q < Mn) ? q : 232 + q;     // 244..255 for q=12..23
    sincospif((float)((ky*w) & 255) * (2.0f/256.0f), &s, &c);
    g_ch[q*Sn + w] = c;
    g_sh[q*Sn + w] = s;
}

// transpose spectral weights to [l][r][k][i][o] and fold 1/65536
__global__ void k_wt(const float* __restrict__ w1r, const float* __restrict__ w1i,
                     const float* __restrict__ w2r, const float* __restrict__ w2i) {
    int flat = blockIdx.x*256 + threadIdx.x;
    if (flat >= WTN) return;
    int o = flat & 31;
    int i = (flat >> 5) & 31;
    int k = (flat >> 10) % Mn;
    int r = (flat / (Mn*Cn*Cn)) % Rn;
    int l =  flat / (Rn*Mn*Cn*Cn);
    int ky = (r < Mn) ? r : r - Mn;
    size_t s = ((((size_t)l*Cn + i)*Cn + o)*Mn + ky)*Mn + k;
    const float sc = 1.0f/65536.0f;
    if (r < Mn) { g_Wtr[flat] = w1r[s]*sc; g_Wti[flat] = w1i[s]*sc; }
    else        { g_Wtr[flat] = w2r[s]*sc; g_Wti[flat] = w2i[s]*sc; }
}

// fused: stageB (DFT over h) + channel mix + inverse-H.  block = (b, k), 24 warps.
__global__ void __launch_bounds__(768) k_modes(int l) {
    extern __shared__ float sm[];
    float* sYr = sm;                       // [32][257]
    float* sYi = sm + Cn*257;
    float* sZr = sm + 2*Cn*257;            // [32][25]
    float* sZi = sZr + Cn*25;
    float* sOr = sZi + Cn*25;              // [32][25]
    float* sOi = sOr + Cn*25;
    int b = blockIdx.x / Mn, k = blockIdx.x % Mn;
    int t = threadIdx.x;

    for (int idx = t; idx < Cn*Sn; idx += 768) {
        int c = idx >> 8, h = idx & 255;
        const float* yp = g_Y + ((size_t)(b*Cn + c)*Sn + h)*(2*Mn);
        sYr[c*257 + h] = yp[k];
        sYi[c*257 + h] = yp[Mn + k];
    }
    __syncthreads();

    int warp = t >> 5, lane = t & 31;
    {   // stage B: Z[c,r] = sum_h Y[c,h] e^{-2pi i ky(r) h/256}; warp=r, lane=c
        int r = warp;
        const float* chp = g_ch + r*Sn;
        const float* shp = g_sh + r*Sn;
        const float* yr = sYr + lane*257;
        const float* yi = sYi + lane*257;
        float zr = 0.f, zi = 0.f;
        #pragma unroll 8
        for (int h = 0; h < Sn; h++) {
            float cv = __ldg(chp + h), sv = __ldg(shp + h);
            float a = yr[h], bb = yi[h];
            zr += a*cv + bb*sv;
            zi += bb*cv - a*sv;
        }
        sZr[lane*25 + r] = zr;
        sZi[lane*25 + r] = zi;
    }
    __syncthreads();
    {   // mix: O[o,r] = sum_i Z[i,r] * W[i,o]  (complex, scale prefolded); warp=r, lane=o
        int r = warp;
        size_t wb = ((size_t)((l*Rn + r)*Mn + k))*(Cn*Cn) + lane;
        const float* wr = g_Wtr + wb;
        const float* wi = g_Wti + wb;
        float orr = 0.f, oii = 0.f;
        #pragma unroll 8
        for (int i = 0; i < Cn; i++) {
            float zr = sZr[i*25 + r], zi = sZi[i*25 + r];
            float ar = wr[(size_t)i*Cn], ai = wi[(size_t)i*Cn];
            orr += zr*ar - zi*ai;
            oii += zr*ai + zi*ar;
        }
        sOr[lane*25 + r] = orr;
        sOi[lane*25 + r] = oii;
    }
    __syncthreads();
    if (t < Sn) {   // inverse H: T[o,h] = sum_r O[o,r] e^{+2pi i ky(r) h/256}; thread=h
        int h = t;
        float cv[Rn], sv[Rn];
        #pragma unroll
        for (int r = 0; r < Rn; r++) { cv[r] = g_ch[r*Sn + h]; sv[r] = g_sh[r*Sn + h]; }
        float* tb = g_T + ((size_t)(b*Sn + h))*Cn*(2*Mn);
        for (int o = 0; o < Cn; o++) {
            float tr = 0.f, ti = 0.f;
            #pragma unroll
            for (int r = 0; r < Rn; r++) {
                float Or = sOr[o*25 + r], Oi = sOi[o*25 + r];
                tr += Or*cv[r] - Oi*sv[r];
                ti += Or*sv[r] + Oi*cv[r];
            }
            tb[o*(2*Mn) + k]      = tr;
            tb[o*(2*Mn) + Mn + k] = ti;
        }
    }
}

// fused per-row kernel. MODE 0: lift + row-DFT. MODE 1: inverse-W + conv + ReLU,
// write h in place, row-DFT for next layer. MODE 2: inverse-W + conv + projection.
template<int MODE>
__global__ void __launch_bounds__(256) k_layer(
    const float* __restrict__ x,
    const float* __restrict__ pw, const float* __restrict__ pb,
    const float* __restrict__ wsw, const float* __restrict__ wsb,
    const float* __restrict__ qw, const float* __restrict__ qb,
    int l, float* __restrict__ out)
{
    extern __shared__ float sm[];
    float* s_v    = sm;                      // [32][260]
    float* s_trig = sm + Cn*260;             // [24][260]
    float* s_t12  = sm + (Cn + Rn)*260;      // [32][24]
    float* s_ws   = s_t12 + Cn*(2*Mn);       // [32][32]
    float* s_wb   = s_ws + Cn*Cn;
    float* s_qw   = s_wb + Cn;

    int t = threadIdx.x;
    int b = blockIdx.x >> 8, y = blockIdx.x & 255;

    for (int i = t; i < Rn*Sn; i += 256)
        s_trig[(i >> 8)*260 + (i & 255)] = g_trig[i];
    if (MODE >= 1) {
        const float* tbp = g_T + (size_t)blockIdx.x * (Cn*2*Mn);
        for (int i = t; i < Cn*2*Mn; i += 256) s_t12[i] = tbp[i];
        for (int i = t; i < Cn*Cn; i += 256)   s_ws[i] = wsw[l*Cn*Cn + i];
        if (t < Cn) { s_wb[t] = wsb[l*Cn + t]; s_qw[t] = qw[t]; }
    }
    __syncthreads();

    int w = t;
    float* hrow = g_h + (((size_t)b*Cn)*Sn + y)*Sn + w;   // + c*Sn*Sn per channel

    if (MODE == 0) {
        float xin = x[(size_t)blockIdx.x*Sn + w];
        float gy = -1.f + (2.f/255.f)*(float)y;
        float gx = -1.f + (2.f/255.f)*(float)w;
        #pragma unroll 8
        for (int c = 0; c < Cn; c++) {
            float v = pw[c*3+0]*xin + pw[c*3+1]*gy + pw[c*3+2]*gx + pb[c];
            hrow[(size_t)c*(Sn*Sn)] = v;
            s_v[c*260 + w] = v;
        }
    } else {
        float cww[Mn], sww[Mn];
        #pragma unroll
        for (int k = 0; k < Mn; k++) {
            cww[k] = s_trig[k*260 + w];
            sww[k] = s_trig[(Mn + k)*260 + w];
        }
        float hin[Cn];
        #pragma unroll
        for (int i = 0; i < Cn; i++) hin[i] = hrow[(size_t)i*(Sn*Sn)];
        float proj = 0.f;
        #pragma unroll 2
        for (int o = 0; o < Cn; o++) {
            const float* wsp = s_ws + o*Cn;
            float acc = s_wb[o];
            #pragma unroll
            for (int i = 0; i < Cn; i++) acc += wsp[i]*hin[i];
            const float* tp = s_t12 + o*(2*Mn);
            float four = tp[0];                       // DC: imag ignored (C2R)
            #pragma unroll
            for (int k = 1; k < Mn; k++)
                four += 2.f*(tp[k]*cww[k] - tp[Mn+k]*sww[k]);
            float v = acc + four;
            if (MODE == 1) {
                v = fmaxf(v, 0.f);
                hrow[(size_t)o*(Sn*Sn)] = v;          // in place: hin already read
                s_v[o*260 + w] = v;
            } else {
                proj += s_qw[o]*v;
            }
        }
        if (MODE == 2) {
            out[(size_t)blockIdx.x*Sn + w] = proj + qb[0];
            return;
        }
    }
    __syncthreads();

    // row DFT: Y[q] = sum_w v(w) trig[q][w]; thread = (o = t>>3, q0 = (t&7)*3)
    int o = t >> 3, q0 = (t & 7)*3;
    const float4* xv4 = (const float4*)(s_v + o*260);
    const float4* t0p = (const float4*)(s_trig + q0*260);
    const float4* t1p = (const float4*)(s_trig + (q0+1)*260);
    const float4* t2p = (const float4*)(s_trig + (q0+2)*260);
    float a0 = 0.f, a1 = 0.f, a2 = 0.f;
    #pragma unroll 8
    for (int w4 = 0; w4 < 64; w4++) {
        float4 xv = xv4[w4];
        float4 u0 = t0p[w4], u1 = t1p[w4], u2 = t2p[w4];
        a0 += xv.x*u0.x + xv.y*u0.y + xv.z*u0.z + xv.w*u0.w;
        a1 += xv.x*u1.x + xv.y*u1.y + xv.z*u1.z + xv.w*u1.w;
        a2 += xv.x*u2.x + xv.y*u2.y + xv.z*u2.z + xv.w*u2.w;
    }
    float sg = (q0 >= Mn) ? -1.f : 1.f;              // Yi = -sum v*sin
    float* yb = g_Y + ((size_t)(b*Cn + o)*Sn + y)*(2*Mn) + q0;
    yb[0] = sg*a0; yb[1] = sg*a1; yb[2] = sg*a2;
}

#define SMEM_LAYER ((Cn*260 + Rn*260 + Cn*2*Mn + Cn*Cn + 2*Cn)*4)
#define SMEM_MODES ((2*Cn*257 + 4*Cn*25)*4)

extern "C" void kernel_launch(void* const* d_in, const int* in_sizes, int n_in,
                              void* d_out, int out_size) {
    (void)in_sizes; (void)n_in; (void)out_size;
    const float* x    = (const float*)d_in[0];
    const float* p_w  = (const float*)d_in[1];
    const float* p_b  = (const float*)d_in[2];
    const float* ws_w = (const float*)d_in[3];
    const float* ws_b = (const float*)d_in[4];
    const float* w1r  = (const float*)d_in[5];
    const float* w1i  = (const float*)d_in[6];
    const float* w2r  = (const float*)d_in[7];
    const float* w2i  = (const float*)d_in[8];
    const float* q_w  = (const float*)d_in[9];
    const float* q_b  = (const float*)d_in[10];
    float* out = (float*)d_out;

    cudaFuncSetAttribute(k_layer<0>, cudaFuncAttributeMaxDynamicSharedMemorySize, SMEM_LAYER);
    cudaFuncSetAttribute(k_layer<1>, cudaFuncAttributeMaxDynamicSharedMemorySize, SMEM_LAYER);
    cudaFuncSetAttribute(k_layer<2>, cudaFuncAttributeMaxDynamicSharedMemorySize, SMEM_LAYER);
    cudaFuncSetAttribute(k_modes,    cudaFuncAttributeMaxDynamicSharedMemorySize, SMEM_MODES);

    k_setup<<<Rn, Sn>>>();
    k_wt<<<(WTN + 255)/256, 256>>>(w1r, w1i, w2r, w2i);
    k_layer<0><<<Bn*Sn, 256, SMEM_LAYER>>>(x, p_w, p_b, nullptr, nullptr, nullptr, nullptr, 0, out);
    for (int l = 0; l < Ln; l++) {
        k_modes<<<Bn*Mn, 768, SMEM_MODES>>>(l);
        if (l < Ln - 1)
            k_layer<1><<<Bn*Sn, 256, SMEM_LAYER>>>(nullptr, nullptr, nullptr,
                                                   ws_w, ws_b, q_w, q_b, l, out);
        else
            k_layer<2><<<Bn*Sn, 256, SMEM_LAYER>>>(nullptr, nullptr, nullptr,
                                                   ws_w, ws_b, q_w, q_b, l, out);
    }
}